// round 8
// baseline (speedup 1.0000x reference)
#include <cuda_runtime.h>
#include <math.h>

// ---------------------------------------------------------------------------
// Problem constants (match reference)
// ---------------------------------------------------------------------------
namespace {
constexpr int B_ = 8, T_ = 1024, D_ = 1024, L_ = 4, H_ = 16, M_ = 134;
constexpr int HD_ = D_ / H_;           // 64
constexpr int ROWS_ = B_ * T_;         // 8192
}

// ---------------------------------------------------------------------------
// Scratch (static __device__ arrays; no allocations allowed)
// ---------------------------------------------------------------------------
__device__ float g_x   [B_ * T_ * D_];        // residual stream (32 MB)
__device__ float g_ln  [B_ * T_ * D_];        // layernorm output (32 MB)
__device__ float g_qkv [B_ * T_ * 3 * D_];    // qkv (96 MB)
__device__ float g_attn[B_ * T_ * D_];        // attention output (32 MB)
__device__ float g_ff  [B_ * T_ * 2 * D_];    // MLP hidden (64 MB)
__device__ float g_emb [B_ * D_];             // fallback emb buffer
__device__ float g_sq  [B_ * M_];             // squared diffs for loss
// tf32-rounded weight copies (rounded once per launch)
__device__ float g_wqkv[L_ * D_ * 3 * D_];    // 48 MB
__device__ float g_wprj[L_ * D_ * D_];        // 16 MB
__device__ float g_wfc [L_ * D_ * 2 * D_];    // 32 MB
__device__ float g_wfcp[L_ * 2 * D_ * D_];    // 32 MB

__device__ __forceinline__ unsigned f2tf(float x) {
    unsigned u;
    asm("cvt.rna.tf32.f32 %0, %1;" : "=r"(u) : "f"(x));
    return u;
}
__device__ __forceinline__ float tfround(float x) {
    return __uint_as_float(f2tf(x));
}

__device__ __forceinline__ void cpa16(float* dst, const float* src) {
    unsigned d = (unsigned)__cvta_generic_to_shared(dst);
    asm volatile("cp.async.cg.shared.global [%0], [%1], 16;\n"
                 :: "r"(d), "l"(src));
}
__device__ __forceinline__ void cpa_commit() {
    asm volatile("cp.async.commit_group;\n");
}
template<int N>
__device__ __forceinline__ void cpa_wait() {
    asm volatile("cp.async.wait_group %0;\n" :: "n"(N));
}

// ---------------------------------------------------------------------------
// Round a tensor to tf32 (float4 grid-stride)
// ---------------------------------------------------------------------------
__global__ void round_kernel(const float* __restrict__ src,
                             float* __restrict__ dst, int n4) {
    int i = blockIdx.x * blockDim.x + threadIdx.x;
    if (i >= n4) return;
    float4 v = ((const float4*)src)[i];
    v.x = tfround(v.x); v.y = tfround(v.y);
    v.z = tfround(v.z); v.w = tfround(v.w);
    ((float4*)dst)[i] = v;
}

// ---------------------------------------------------------------------------
// x = X + wpe (broadcast over batch)
// ---------------------------------------------------------------------------
__global__ void posadd_kernel(const float* __restrict__ X,
                              const float* __restrict__ wpe) {
    int i = blockIdx.x * blockDim.x + threadIdx.x;   // < B*T*D = 8388608
    g_x[i] = X[i] + wpe[i & (T_ * D_ - 1)];
}

// ---------------------------------------------------------------------------
// LayerNorm over D=1024, one block (256 threads) per row.
// RND: emit tf32-rounded output (when the only consumer is a GEMM A operand)
// ---------------------------------------------------------------------------
template<bool PRE, bool WB, bool POST, bool RND>
__global__ void ln_kernel(const float* __restrict__ in,
                          float* __restrict__ wbp,
                          const float* __restrict__ w,
                          const float* __restrict__ bb,
                          float* __restrict__ out) {
    int row = blockIdx.x;
    int tid = threadIdx.x;                 // 256
    const float* xr = in + (size_t)row * D_;

    float v[4];
    float s = 0.f, s2 = 0.f;
#pragma unroll
    for (int i = 0; i < 4; i++) {
        float t = xr[tid + i * 256];
        if (PRE) t = fmaxf(t, 0.f);
        v[i] = t;
        s += t;
        s2 += t * t;
    }

    __shared__ float sa[8], sb[8];
    int lane = tid & 31, wid = tid >> 5;
#pragma unroll
    for (int o = 16; o; o >>= 1) {
        s  += __shfl_down_sync(0xffffffffu, s,  o);
        s2 += __shfl_down_sync(0xffffffffu, s2, o);
    }
    if (lane == 0) { sa[wid] = s; sb[wid] = s2; }
    __syncthreads();
    if (wid == 0) {
        s  = (lane < 8) ? sa[lane] : 0.f;
        s2 = (lane < 8) ? sb[lane] : 0.f;
#pragma unroll
        for (int o = 4; o; o >>= 1) {
            s  += __shfl_down_sync(0xffffffffu, s,  o);
            s2 += __shfl_down_sync(0xffffffffu, s2, o);
        }
        if (lane == 0) { sa[0] = s; sb[0] = s2; }
    }
    __syncthreads();

    float mu  = sa[0] * (1.f / D_);
    float var = sb[0] * (1.f / D_) - mu * mu;
    float inv = rsqrtf(var + 1e-5f);

    float* orow = out + (size_t)row * D_;
#pragma unroll
    for (int i = 0; i < 4; i++) {
        int c = tid + i * 256;
        float o = (v[i] - mu) * inv * w[c] + bb[c];
        if (POST) o = fmaxf(o, 0.f);
        if (RND) o = tfround(o);
        orow[c] = o;
        if (WB) wbp[(size_t)row * D_ + c] = v[i];
    }
}

// ---------------------------------------------------------------------------
// TF32 tensor-core GEMM, 4-stage cp.async pipeline. Inputs PRE-ROUNDED to
// tf32 bit patterns, so the mainloop is pure LDS + HMMA (no cvt).
// C[M,N] = epi(A[M,K] @ Bw[K,N] + bias (+ res)); RNDO rounds output to tf32.
// 128x128x16 tile, 256 threads (8 warps, 2x4), warp tile 64x32.
// ---------------------------------------------------------------------------
namespace {
constexpr int GBM = 128, GBN = 128, GBK = 16, GSTG = 4;
constexpr int AS_STR = 20;               // floats/row (80B, 16B-aligned, cf-free)
constexpr int BS_STR = 136;              // floats/row (544B, 16B-aligned, cf-free)
constexpr int A_STG = GBM * AS_STR;      // 2560 floats
constexpr int B_STG = GBK * BS_STR;      // 2176 floats
constexpr int GEMM_SMEM = GSTG * (A_STG + B_STG) * 4;   // 75776 bytes
}

template<bool RELU, bool RES, bool RNDO>
__global__ void __launch_bounds__(256)
gemm_tf32_kernel(int Nn, int Kk,
                 const float* __restrict__ A,
                 const float* __restrict__ Bw,
                 const float* __restrict__ bias,
                 const float* __restrict__ res,
                 float* __restrict__ C) {
    extern __shared__ float sm[];
    float* smA = sm;                       // [GSTG][A_STG]
    float* smB = sm + GSTG * A_STG;        // [GSTG][B_STG]

    int tid = threadIdx.x, lane = tid & 31, warp = tid >> 5;
    int wr = warp >> 2, wc = warp & 3;     // 2 x 4 warp grid
    int g = lane >> 2, t4 = lane & 3;

    const float* Ab = A + (size_t)(blockIdx.y * GBM) * Kk;
    const float* Bb = Bw + blockIdx.x * GBN;

    int aRow = tid >> 2, aCol = (tid & 3) * 4;   // A: 64 rows/pass x 16 cols
    int bRow = tid >> 5, bCol = (tid & 31) * 4;  // B: 8 rows/pass x 128 cols

    int nTiles = Kk / GBK;

    // prologue: issue first 3 stages
#pragma unroll
    for (int p = 0; p < GSTG - 1; p++) {
        float* As = smA + p * A_STG;
        float* Bs = smB + p * B_STG;
        int k0 = p * GBK;
        cpa16(As + aRow * AS_STR + aCol,        Ab + (size_t)aRow * Kk + k0 + aCol);
        cpa16(As + (aRow + 64) * AS_STR + aCol, Ab + (size_t)(aRow + 64) * Kk + k0 + aCol);
        cpa16(Bs + bRow * BS_STR + bCol,        Bb + (size_t)(k0 + bRow) * Nn + bCol);
        cpa16(Bs + (bRow + 8) * BS_STR + bCol,  Bb + (size_t)(k0 + bRow + 8) * Nn + bCol);
        cpa_commit();
    }

    float acc[4][4][4] = {};

    for (int it = 0; it < nTiles; it++) {
        cpa_wait<GSTG - 2>();    // oldest stage (it % GSTG) landed
        __syncthreads();

        const float* As = smA + (it & (GSTG - 1)) * A_STG;
        const float* Bs = smB + (it & (GSTG - 1)) * B_STG;

#pragma unroll
        for (int ks = 0; ks < GBK; ks += 8) {
            unsigned af[4][4], bf[4][2];
#pragma unroll
            for (int mt = 0; mt < 4; mt++) {
                int m = wr * 64 + mt * 16;
                af[mt][0] = __float_as_uint(As[(m + g) * AS_STR + ks + t4]);
                af[mt][1] = __float_as_uint(As[(m + g + 8) * AS_STR + ks + t4]);
                af[mt][2] = __float_as_uint(As[(m + g) * AS_STR + ks + t4 + 4]);
                af[mt][3] = __float_as_uint(As[(m + g + 8) * AS_STR + ks + t4 + 4]);
            }
#pragma unroll
            for (int nt = 0; nt < 4; nt++) {
                int n = wc * 32 + nt * 8;
                bf[nt][0] = __float_as_uint(Bs[(ks + t4) * BS_STR + n + g]);
                bf[nt][1] = __float_as_uint(Bs[(ks + t4 + 4) * BS_STR + n + g]);
            }
#pragma unroll
            for (int mt = 0; mt < 4; mt++)
#pragma unroll
                for (int nt = 0; nt < 4; nt++) {
                    asm volatile(
                        "mma.sync.aligned.m16n8k8.row.col.f32.tf32.tf32.f32 "
                        "{%0,%1,%2,%3}, {%4,%5,%6,%7}, {%8,%9}, {%0,%1,%2,%3};"
                        : "+f"(acc[mt][nt][0]), "+f"(acc[mt][nt][1]),
                          "+f"(acc[mt][nt][2]), "+f"(acc[mt][nt][3])
                        : "r"(af[mt][0]), "r"(af[mt][1]),
                          "r"(af[mt][2]), "r"(af[mt][3]),
                          "r"(bf[nt][0]), "r"(bf[nt][1]));
                }
        }

        // issue loads for tile it+3
        int nx = it + GSTG - 1;
        if (nx < nTiles) {
            float* Asw = smA + (nx & (GSTG - 1)) * A_STG;
            float* Bsw = smB + (nx & (GSTG - 1)) * B_STG;
            int k0 = nx * GBK;
            cpa16(Asw + aRow * AS_STR + aCol,        Ab + (size_t)aRow * Kk + k0 + aCol);
            cpa16(Asw + (aRow + 64) * AS_STR + aCol, Ab + (size_t)(aRow + 64) * Kk + k0 + aCol);
            cpa16(Bsw + bRow * BS_STR + bCol,        Bb + (size_t)(k0 + bRow) * Nn + bCol);
            cpa16(Bsw + (bRow + 8) * BS_STR + bCol,  Bb + (size_t)(k0 + bRow + 8) * Nn + bCol);
        }
        cpa_commit();   // one group per iter keeps wait_group counting uniform
    }

    // epilogue: c0,c1 -> (row g, cols 2t4,2t4+1); c2,c3 -> (row g+8, same)
    int gr = blockIdx.y * GBM + wr * 64 + g;
    int gc = blockIdx.x * GBN + wc * 32;
#pragma unroll
    for (int mt = 0; mt < 4; mt++) {
#pragma unroll
        for (int nt = 0; nt < 4; nt++) {
            int c = gc + nt * 8 + 2 * t4;
            float b0 = bias[c], b1 = bias[c + 1];
#pragma unroll
            for (int half = 0; half < 2; half++) {
                int r = gr + mt * 16 + half * 8;
                size_t o = (size_t)r * Nn + c;
                float v0 = acc[mt][nt][half * 2 + 0] + b0;
                float v1 = acc[mt][nt][half * 2 + 1] + b1;
                if (RES) { v0 += res[o]; v1 += res[o + 1]; }
                if (RELU) { v0 = fmaxf(v0, 0.f); v1 = fmaxf(v1, 0.f); }
                if (RNDO) { v0 = tfround(v0); v1 = tfround(v1); }
                *(float2*)(C + o) = make_float2(v0, v1);
            }
        }
    }
}

// ---------------------------------------------------------------------------
// Tensor-core causal ReLU attention: y = (causal_relu(Q K^T / 8)) V
// Output rounded to tf32 (sole consumer is proj GEMM A).
// ---------------------------------------------------------------------------
__global__ void __launch_bounds__(128)
attn_tc_kernel(const float* __restrict__ qkv, float* __restrict__ y) {
    constexpr int QT = 64, KT = 32;
    __shared__ unsigned Qs[QT][68];
    __shared__ unsigned Ks[KT][68];
    __shared__ unsigned Vs[KT][72];
    __shared__ unsigned Ss[4][16][36];

    int q0 = blockIdx.x * QT;
    int h  = blockIdx.y;
    int b  = blockIdx.z;
    int tid = threadIdx.x, lane = tid & 31, w = tid >> 5;
    int g = lane >> 2, t4 = lane & 3;

    const size_t rs = 3 * D_;
    const float* base = qkv + (size_t)b * T_ * rs + h * HD_;

    // Load Q tile (64 x 64), convert to tf32
    {
        int c4 = (tid & 15) * 4, qr = tid >> 4;
#pragma unroll
        for (int p = 0; p < 8; p++) {
            int q = qr + p * 8;
            float4 v = *(const float4*)(base + (size_t)(q0 + q) * rs + c4);
            Qs[q][c4 + 0] = f2tf(v.x);
            Qs[q][c4 + 1] = f2tf(v.y);
            Qs[q][c4 + 2] = f2tf(v.z);
            Qs[q][c4 + 3] = f2tf(v.w);
        }
    }

    float oacc[8][4] = {};
    int qa = q0 + w * 16 + g;   // absolute q of c-rows 0/1 (row g)

    for (int kbase = 0; kbase < q0 + QT; kbase += KT) {
        __syncthreads();   // prior-iter PV done with Ks/Vs; Q ready on iter 0
        {
            int c4 = (tid & 15) * 4, kr = tid >> 4;
#pragma unroll
            for (int p = 0; p < 4; p++) {
                int k = kr + p * 8;
                const float* rp = base + (size_t)(kbase + k) * rs + c4;
                float4 kv = *(const float4*)(rp + D_);
                float4 vv = *(const float4*)(rp + 2 * D_);
                Ks[k][c4 + 0] = f2tf(kv.x);
                Ks[k][c4 + 1] = f2tf(kv.y);
                Ks[k][c4 + 2] = f2tf(kv.z);
                Ks[k][c4 + 3] = f2tf(kv.w);
                Vs[k][c4 + 0] = f2tf(vv.x);
                Vs[k][c4 + 1] = f2tf(vv.y);
                Vs[k][c4 + 2] = f2tf(vv.z);
                Vs[k][c4 + 3] = f2tf(vv.w);
            }
        }
        __syncthreads();

        // --- S = Q K^T (M=16, N=32, K=64) ---
        float sacc[4][4] = {};
#pragma unroll
        for (int ks = 0; ks < HD_; ks += 8) {
            unsigned a0 = Qs[w * 16 + g][ks + t4];
            unsigned a1 = Qs[w * 16 + g + 8][ks + t4];
            unsigned a2 = Qs[w * 16 + g][ks + t4 + 4];
            unsigned a3 = Qs[w * 16 + g + 8][ks + t4 + 4];
#pragma unroll
            for (int nt = 0; nt < 4; nt++) {
                unsigned b0 = Ks[nt * 8 + g][ks + t4];
                unsigned b1 = Ks[nt * 8 + g][ks + t4 + 4];
                asm volatile(
                    "mma.sync.aligned.m16n8k8.row.col.f32.tf32.tf32.f32 "
                    "{%0,%1,%2,%3}, {%4,%5,%6,%7}, {%8,%9}, {%0,%1,%2,%3};"
                    : "+f"(sacc[nt][0]), "+f"(sacc[nt][1]),
                      "+f"(sacc[nt][2]), "+f"(sacc[nt][3])
                    : "r"(a0), "r"(a1), "r"(a2), "r"(a3), "r"(b0), "r"(b1));
            }
        }

        // scale, causal mask, relu -> Ss (tf32)
#pragma unroll
        for (int nt = 0; nt < 4; nt++) {
            int ka = kbase + nt * 8 + 2 * t4;
            float s0 = (ka     <= qa)     ? fmaxf(sacc[nt][0] * 0.125f, 0.f) : 0.f;
            float s1 = (ka + 1 <= qa)     ? fmaxf(sacc[nt][1] * 0.125f, 0.f) : 0.f;
            float s2 = (ka     <= qa + 8) ? fmaxf(sacc[nt][2] * 0.125f, 0.f) : 0.f;
            float s3 = (ka + 1 <= qa + 8) ? fmaxf(sacc[nt][3] * 0.125f, 0.f) : 0.f;
            Ss[w][g][nt * 8 + 2 * t4]         = f2tf(s0);
            Ss[w][g][nt * 8 + 2 * t4 + 1]     = f2tf(s1);
            Ss[w][g + 8][nt * 8 + 2 * t4]     = f2tf(s2);
            Ss[w][g + 8][nt * 8 + 2 * t4 + 1] = f2tf(s3);
        }
        __syncwarp();

        // --- oacc += S @ V (M=16, N=64, K=32) ---
#pragma unroll
        for (int ks = 0; ks < KT; ks += 8) {
            unsigned a0 = Ss[w][g][ks + t4];
            unsigned a1 = Ss[w][g + 8][ks + t4];
            unsigned a2 = Ss[w][g][ks + t4 + 4];
            unsigned a3 = Ss[w][g + 8][ks + t4 + 4];
#pragma unroll
            for (int nt = 0; nt < 8; nt++) {
                unsigned b0 = Vs[ks + t4][nt * 8 + g];
                unsigned b1 = Vs[ks + t4 + 4][nt * 8 + g];
                asm volatile(
                    "mma.sync.aligned.m16n8k8.row.col.f32.tf32.tf32.f32 "
                    "{%0,%1,%2,%3}, {%4,%5,%6,%7}, {%8,%9}, {%0,%1,%2,%3};"
                    : "+f"(oacc[nt][0]), "+f"(oacc[nt][1]),
                      "+f"(oacc[nt][2]), "+f"(oacc[nt][3])
                    : "r"(a0), "r"(a1), "r"(a2), "r"(a3), "r"(b0), "r"(b1));
            }
        }
    }

    // epilogue: warp owns rows [w*16, w*16+16), cols [0, 64); round to tf32
    float* yb = y + ((size_t)(b * T_ + q0 + w * 16) * D_) + h * HD_;
#pragma unroll
    for (int nt = 0; nt < 8; nt++) {
        int c = nt * 8 + 2 * t4;
        *(float2*)(yb + (size_t)g * D_ + c) =
            make_float2(tfround(oacc[nt][0]), tfround(oacc[nt][1]));
        *(float2*)(yb + (size_t)(g + 8) * D_ + c) =
            make_float2(tfround(oacc[nt][2]), tfround(oacc[nt][3]));
    }
}

// ---------------------------------------------------------------------------
// emb[b,d] = mean_t ln[b,t,d]
// ---------------------------------------------------------------------------
__global__ void mean_kernel(const float* __restrict__ ln,
                            float* __restrict__ embp) {
    int i = blockIdx.x * blockDim.x + threadIdx.x;
    if (i >= B_ * D_) return;
    int b = i >> 10, d = i & 1023;
    const float* p = ln + (size_t)b * T_ * D_ + d;
    float s = 0.f;
    for (int t = 0; t < T_; t++) s += p[(size_t)t * D_];
    embp[i] = s * (1.f / T_);
}

// ---------------------------------------------------------------------------
// logits = relu(emb @ head_w + head_b); store (logits - Y)^2
// ---------------------------------------------------------------------------
__global__ void head_kernel(const float* __restrict__ embp,
                            const float* __restrict__ hw,
                            const float* __restrict__ hb,
                            const float* __restrict__ Y) {
    int i = blockIdx.x * blockDim.x + threadIdx.x;
    if (i >= B_ * M_) return;
    int b = i / M_, m = i % M_;
    const float* e = embp + b * D_;
    float s = hb[m];
    for (int k = 0; k < D_; k++) s += e[k] * hw[k * M_ + m];
    s = fmaxf(s, 0.f);
    float df = s - Y[i];
    g_sq[i] = df * df;
}

// ---------------------------------------------------------------------------
// loss = 50 * sqrt(mean(sq))
// ---------------------------------------------------------------------------
__global__ void loss_kernel(float* __restrict__ outp) {
    __shared__ float sm[256];
    int tid = threadIdx.x;
    float s = 0.f;
    for (int i = tid; i < B_ * M_; i += 256) s += g_sq[i];
    sm[tid] = s;
    __syncthreads();
    for (int o = 128; o; o >>= 1) {
        if (tid < o) sm[tid] += sm[tid + o];
        __syncthreads();
    }
    if (tid == 0) outp[0] = 50.f * sqrtf(sm[0] / (float)(B_ * M_));
}

// ---------------------------------------------------------------------------
// Host driver (graph-capturable: kernel launches only)
// ---------------------------------------------------------------------------
extern "C" void kernel_launch(void* const* d_in, const int* in_sizes, int n_in,
                              void* d_out, int out_size) {
    const float* X      = (const float*)d_in[0];
    const float* Y      = (const float*)d_in[1];
    const float* wpe    = (const float*)d_in[2];
    const float* ln1_w  = (const float*)d_in[3];
    const float* ln1_b  = (const float*)d_in[4];
    const float* attn_w = (const float*)d_in[5];
    const float* attn_b = (const float*)d_in[6];
    const float* proj_w = (const float*)d_in[7];
    const float* proj_b = (const float*)d_in[8];
    const float* ln2_w  = (const float*)d_in[9];
    const float* ln2_b  = (const float*)d_in[10];
    const float* fc_w   = (const float*)d_in[11];
    const float* fc_b   = (const float*)d_in[12];
    const float* fcp_w  = (const float*)d_in[13];
    const float* fcp_b  = (const float*)d_in[14];
    const float* lnf_w  = (const float*)d_in[15];
    const float* lnf_b  = (const float*)d_in[16];
    const float* head_w = (const float*)d_in[17];
    const float* head_b = (const float*)d_in[18];
    float* out = (float*)d_out;

    float *x, *ln, *qkv, *attn, *ff, *emb;
    float *wqkv, *wprj, *wfc, *wfcp;
    cudaGetSymbolAddress((void**)&x,    g_x);
    cudaGetSymbolAddress((void**)&ln,   g_ln);
    cudaGetSymbolAddress((void**)&qkv,  g_qkv);
    cudaGetSymbolAddress((void**)&attn, g_attn);
    cudaGetSymbolAddress((void**)&ff,   g_ff);
    cudaGetSymbolAddress((void**)&emb,  g_emb);
    cudaGetSymbolAddress((void**)&wqkv, g_wqkv);
    cudaGetSymbolAddress((void**)&wprj, g_wprj);
    cudaGetSymbolAddress((void**)&wfc,  g_wfc);
    cudaGetSymbolAddress((void**)&wfcp, g_wfcp);

    cudaFuncSetAttribute(gemm_tf32_kernel<true, false, false>,
                         cudaFuncAttributeMaxDynamicSharedMemorySize, GEMM_SMEM);
    cudaFuncSetAttribute(gemm_tf32_kernel<true, false, true>,
                         cudaFuncAttributeMaxDynamicSharedMemorySize, GEMM_SMEM);
    cudaFuncSetAttribute(gemm_tf32_kernel<false, true, false>,
                         cudaFuncAttributeMaxDynamicSharedMemorySize, GEMM_SMEM);

    // one-time (per launch) weight rounding to tf32
    {
        int n;
        n = L_ * D_ * 3 * D_ / 4;
        round_kernel<<<(n + 255) / 256, 256>>>(attn_w, wqkv, n);
        n = L_ * D_ * D_ / 4;
        round_kernel<<<(n + 255) / 256, 256>>>(proj_w, wprj, n);
        n = L_ * D_ * 2 * D_ / 4;
        round_kernel<<<(n + 255) / 256, 256>>>(fc_w, wfc, n);
        n = L_ * 2 * D_ * D_ / 4;
        round_kernel<<<(n + 255) / 256, 256>>>(fcp_w, wfcp, n);
    }

    posadd_kernel<<<B_ * T_ * D_ / 256, 256>>>(X, wpe);

    dim3 gQKV(3 * D_ / 128, ROWS_ / 128);
    dim3 gD  (D_     / 128, ROWS_ / 128);
    dim3 gFF (2 * D_ / 128, ROWS_ / 128);
    dim3 gAtt(T_ / 64, H_, B_);

    for (int i = 0; i < L_; i++) {
        // x = relu(x); ln = tf32(LN(x))
        ln_kernel<true, true, false, true><<<ROWS_, 256>>>(
            x, x, ln1_w + i * D_, ln1_b + i * D_, ln);
        // qkv = relu(ln @ Wqkv + b)   (attn rounds q/k/v internally)
        gemm_tf32_kernel<true, false, false><<<gQKV, 256, GEMM_SMEM>>>(
            3 * D_, D_, ln,
            wqkv + (size_t)i * D_ * 3 * D_, attn_b + i * 3 * D_, nullptr, qkv);
        // y = tf32(causal-relu attention)
        attn_tc_kernel<<<gAtt, 128>>>(qkv, attn);
        // x = x + y @ Wproj + b   (residual: full fp32)
        gemm_tf32_kernel<false, true, false><<<gD, 256, GEMM_SMEM>>>(
            D_, D_, attn,
            wprj + (size_t)i * D_ * D_, proj_b + i * D_, x, x);
        // h = tf32(LN2(x))
        ln_kernel<false, false, false, true><<<ROWS_, 256>>>(
            x, nullptr, ln2_w + i * D_, ln2_b + i * D_, ln);
        // ff = tf32(relu(h @ Wfc + b))
        gemm_tf32_kernel<true, false, true><<<gFF, 256, GEMM_SMEM>>>(
            2 * D_, D_, ln,
            wfc + (size_t)i * D_ * 2 * D_, fc_b + i * 2 * D_, nullptr, ff);
        // x = x + ff @ Wfcp + b
        gemm_tf32_kernel<false, true, false><<<gD, 256, GEMM_SMEM>>>(
            D_, 2 * D_, ff,
            wfcp + (size_t)i * 2 * D_ * D_, fcp_b + i * D_, x, x);
    }

    // x = relu(x); ln = relu(LN_f(x))  -- NOT rounded (feeds emb output)
    ln_kernel<true, false, true, false><<<ROWS_, 256>>>(x, nullptr, lnf_w, lnf_b, ln);

    float* embp = (out_size >= B_ * D_) ? out : emb;
    mean_kernel<<<(B_ * D_ + 255) / 256, 256>>>(ln, embp);

    head_kernel<<<(B_ * M_ + 255) / 256, 256>>>(embp, head_w, head_b, Y);

    if (out_size >= B_ * D_ + 1) {
        loss_kernel<<<1, 256>>>(out + B_ * D_);
    } else if (out_size < B_ * D_) {
        loss_kernel<<<1, 256>>>(out);   // loss-only output layout
    }
}

// round 9
// speedup vs baseline: 1.0001x; 1.0001x over previous
#include <cuda_runtime.h>
#include <math.h>

// ---------------------------------------------------------------------------
// Problem constants (match reference)
// ---------------------------------------------------------------------------
namespace {
constexpr int B_ = 8, T_ = 1024, D_ = 1024, L_ = 4, H_ = 16, M_ = 134;
constexpr int HD_ = D_ / H_;           // 64
constexpr int ROWS_ = B_ * T_;         // 8192
}

// ---------------------------------------------------------------------------
// Scratch (static __device__ arrays; no allocations allowed)
// ---------------------------------------------------------------------------
__device__ float g_x   [B_ * T_ * D_];        // residual stream (32 MB)
__device__ float g_ln  [B_ * T_ * D_];        // layernorm output (32 MB)
__device__ float g_qkv [B_ * T_ * 3 * D_];    // qkv (96 MB)
__device__ float g_attn[B_ * T_ * D_];        // attention output (32 MB)
__device__ float g_ff  [B_ * T_ * 2 * D_];    // MLP hidden (64 MB)
__device__ float g_emb [B_ * D_];             // fallback emb buffer
__device__ float g_sq  [B_ * M_];             // squared diffs for loss
// tf32-rounded weight copies (rounded once per launch)
__device__ float g_wqkv[L_ * D_ * 3 * D_];    // 48 MB
__device__ float g_wprj[L_ * D_ * D_];        // 16 MB
__device__ float g_wfc [L_ * D_ * 2 * D_];    // 32 MB
__device__ float g_wfcp[L_ * 2 * D_ * D_];    // 32 MB

__device__ __forceinline__ unsigned f2tf(float x) {
    unsigned u;
    asm("cvt.rna.tf32.f32 %0, %1;" : "=r"(u) : "f"(x));
    return u;
}
__device__ __forceinline__ float tfround(float x) {
    return __uint_as_float(f2tf(x));
}

__device__ __forceinline__ void cpa16(float* dst, const float* src) {
    unsigned d = (unsigned)__cvta_generic_to_shared(dst);
    asm volatile("cp.async.cg.shared.global [%0], [%1], 16;\n"
                 :: "r"(d), "l"(src));
}
__device__ __forceinline__ void cpa_commit() {
    asm volatile("cp.async.commit_group;\n");
}
template<int N>
__device__ __forceinline__ void cpa_wait() {
    asm volatile("cp.async.wait_group %0;\n" :: "n"(N));
}

// ---------------------------------------------------------------------------
// Round a tensor to tf32 (float4 grid-stride)
// ---------------------------------------------------------------------------
__global__ void round_kernel(const float* __restrict__ src,
                             float* __restrict__ dst, int n4) {
    int i = blockIdx.x * blockDim.x + threadIdx.x;
    if (i >= n4) return;
    float4 v = ((const float4*)src)[i];
    v.x = tfround(v.x); v.y = tfround(v.y);
    v.z = tfround(v.z); v.w = tfround(v.w);
    ((float4*)dst)[i] = v;
}

// ---------------------------------------------------------------------------
// x = X + wpe (broadcast over batch)
// ---------------------------------------------------------------------------
__global__ void posadd_kernel(const float* __restrict__ X,
                              const float* __restrict__ wpe) {
    int i = blockIdx.x * blockDim.x + threadIdx.x;   // < B*T*D = 8388608
    g_x[i] = X[i] + wpe[i & (T_ * D_ - 1)];
}

// ---------------------------------------------------------------------------
// LayerNorm over D=1024, one block (256 threads) per row.
// RND: emit tf32-rounded output (when the only consumer is a GEMM A operand)
// ---------------------------------------------------------------------------
template<bool PRE, bool WB, bool POST, bool RND>
__global__ void ln_kernel(const float* __restrict__ in,
                          float* __restrict__ wbp,
                          const float* __restrict__ w,
                          const float* __restrict__ bb,
                          float* __restrict__ out) {
    int row = blockIdx.x;
    int tid = threadIdx.x;                 // 256
    const float* xr = in + (size_t)row * D_;

    float v[4];
    float s = 0.f, s2 = 0.f;
#pragma unroll
    for (int i = 0; i < 4; i++) {
        float t = xr[tid + i * 256];
        if (PRE) t = fmaxf(t, 0.f);
        v[i] = t;
        s += t;
        s2 += t * t;
    }

    __shared__ float sa[8], sb[8];
    int lane = tid & 31, wid = tid >> 5;
#pragma unroll
    for (int o = 16; o; o >>= 1) {
        s  += __shfl_down_sync(0xffffffffu, s,  o);
        s2 += __shfl_down_sync(0xffffffffu, s2, o);
    }
    if (lane == 0) { sa[wid] = s; sb[wid] = s2; }
    __syncthreads();
    if (wid == 0) {
        s  = (lane < 8) ? sa[lane] : 0.f;
        s2 = (lane < 8) ? sb[lane] : 0.f;
#pragma unroll
        for (int o = 4; o; o >>= 1) {
            s  += __shfl_down_sync(0xffffffffu, s,  o);
            s2 += __shfl_down_sync(0xffffffffu, s2, o);
        }
        if (lane == 0) { sa[0] = s; sb[0] = s2; }
    }
    __syncthreads();

    float mu  = sa[0] * (1.f / D_);
    float var = sb[0] * (1.f / D_) - mu * mu;
    float inv = rsqrtf(var + 1e-5f);

    float* orow = out + (size_t)row * D_;
#pragma unroll
    for (int i = 0; i < 4; i++) {
        int c = tid + i * 256;
        float o = (v[i] - mu) * inv * w[c] + bb[c];
        if (POST) o = fmaxf(o, 0.f);
        if (RND) o = tfround(o);
        orow[c] = o;
        if (WB) wbp[(size_t)row * D_ + c] = v[i];
    }
}

// ---------------------------------------------------------------------------
// TF32 tensor-core GEMM, 4-stage cp.async pipeline. Inputs PRE-ROUNDED to
// tf32 bit patterns, so the mainloop is pure LDS + HMMA (no cvt).
// C[M,N] = epi(A[M,K] @ Bw[K,N] + bias (+ res)); RNDO rounds output to tf32.
// 128x128x16 tile, 256 threads (8 warps, 2x4), warp tile 64x32.
// ---------------------------------------------------------------------------
namespace {
constexpr int GBM = 128, GBN = 128, GBK = 16, GSTG = 4;
constexpr int AS_STR = 20;               // floats/row (80B, 16B-aligned, cf-free)
constexpr int BS_STR = 136;              // floats/row (544B, 16B-aligned, cf-free)
constexpr int A_STG = GBM * AS_STR;      // 2560 floats
constexpr int B_STG = GBK * BS_STR;      // 2176 floats
constexpr int GEMM_SMEM = GSTG * (A_STG + B_STG) * 4;   // 75776 bytes
}

template<bool RELU, bool RES, bool RNDO>
__global__ void __launch_bounds__(256)
gemm_tf32_kernel(int Nn, int Kk,
                 const float* __restrict__ A,
                 const float* __restrict__ Bw,
                 const float* __restrict__ bias,
                 const float* __restrict__ res,
                 float* __restrict__ C) {
    extern __shared__ float sm[];
    float* smA = sm;                       // [GSTG][A_STG]
    float* smB = sm + GSTG * A_STG;        // [GSTG][B_STG]

    int tid = threadIdx.x, lane = tid & 31, warp = tid >> 5;
    int wr = warp >> 2, wc = warp & 3;     // 2 x 4 warp grid
    int g = lane >> 2, t4 = lane & 3;

    const float* Ab = A + (size_t)(blockIdx.y * GBM) * Kk;
    const float* Bb = Bw + blockIdx.x * GBN;

    int aRow = tid >> 2, aCol = (tid & 3) * 4;   // A: 64 rows/pass x 16 cols
    int bRow = tid >> 5, bCol = (tid & 31) * 4;  // B: 8 rows/pass x 128 cols

    int nTiles = Kk / GBK;

    // prologue: issue first 3 stages
#pragma unroll
    for (int p = 0; p < GSTG - 1; p++) {
        float* As = smA + p * A_STG;
        float* Bs = smB + p * B_STG;
        int k0 = p * GBK;
        cpa16(As + aRow * AS_STR + aCol,        Ab + (size_t)aRow * Kk + k0 + aCol);
        cpa16(As + (aRow + 64) * AS_STR + aCol, Ab + (size_t)(aRow + 64) * Kk + k0 + aCol);
        cpa16(Bs + bRow * BS_STR + bCol,        Bb + (size_t)(k0 + bRow) * Nn + bCol);
        cpa16(Bs + (bRow + 8) * BS_STR + bCol,  Bb + (size_t)(k0 + bRow + 8) * Nn + bCol);
        cpa_commit();
    }

    float acc[4][4][4] = {};

    for (int it = 0; it < nTiles; it++) {
        cpa_wait<GSTG - 2>();    // oldest stage (it % GSTG) landed
        __syncthreads();

        const float* As = smA + (it & (GSTG - 1)) * A_STG;
        const float* Bs = smB + (it & (GSTG - 1)) * B_STG;

#pragma unroll
        for (int ks = 0; ks < GBK; ks += 8) {
            unsigned af[4][4], bf[4][2];
#pragma unroll
            for (int mt = 0; mt < 4; mt++) {
                int m = wr * 64 + mt * 16;
                af[mt][0] = __float_as_uint(As[(m + g) * AS_STR + ks + t4]);
                af[mt][1] = __float_as_uint(As[(m + g + 8) * AS_STR + ks + t4]);
                af[mt][2] = __float_as_uint(As[(m + g) * AS_STR + ks + t4 + 4]);
                af[mt][3] = __float_as_uint(As[(m + g + 8) * AS_STR + ks + t4 + 4]);
            }
#pragma unroll
            for (int nt = 0; nt < 4; nt++) {
                int n = wc * 32 + nt * 8;
                bf[nt][0] = __float_as_uint(Bs[(ks + t4) * BS_STR + n + g]);
                bf[nt][1] = __float_as_uint(Bs[(ks + t4 + 4) * BS_STR + n + g]);
            }
#pragma unroll
            for (int mt = 0; mt < 4; mt++)
#pragma unroll
                for (int nt = 0; nt < 4; nt++) {
                    asm volatile(
                        "mma.sync.aligned.m16n8k8.row.col.f32.tf32.tf32.f32 "
                        "{%0,%1,%2,%3}, {%4,%5,%6,%7}, {%8,%9}, {%0,%1,%2,%3};"
                        : "+f"(acc[mt][nt][0]), "+f"(acc[mt][nt][1]),
                          "+f"(acc[mt][nt][2]), "+f"(acc[mt][nt][3])
                        : "r"(af[mt][0]), "r"(af[mt][1]),
                          "r"(af[mt][2]), "r"(af[mt][3]),
                          "r"(bf[nt][0]), "r"(bf[nt][1]));
                }
        }

        // issue loads for tile it+3
        int nx = it + GSTG - 1;
        if (nx < nTiles) {
            float* Asw = smA + (nx & (GSTG - 1)) * A_STG;
            float* Bsw = smB + (nx & (GSTG - 1)) * B_STG;
            int k0 = nx * GBK;
            cpa16(Asw + aRow * AS_STR + aCol,        Ab + (size_t)aRow * Kk + k0 + aCol);
            cpa16(Asw + (aRow + 64) * AS_STR + aCol, Ab + (size_t)(aRow + 64) * Kk + k0 + aCol);
            cpa16(Bsw + bRow * BS_STR + bCol,        Bb + (size_t)(k0 + bRow) * Nn + bCol);
            cpa16(Bsw + (bRow + 8) * BS_STR + bCol,  Bb + (size_t)(k0 + bRow + 8) * Nn + bCol);
        }
        cpa_commit();   // one group per iter keeps wait_group counting uniform
    }

    // epilogue: c0,c1 -> (row g, cols 2t4,2t4+1); c2,c3 -> (row g+8, same)
    int gr = blockIdx.y * GBM + wr * 64 + g;
    int gc = blockIdx.x * GBN + wc * 32;
#pragma unroll
    for (int mt = 0; mt < 4; mt++) {
#pragma unroll
        for (int nt = 0; nt < 4; nt++) {
            int c = gc + nt * 8 + 2 * t4;
            float b0 = bias[c], b1 = bias[c + 1];
#pragma unroll
            for (int half = 0; half < 2; half++) {
                int r = gr + mt * 16 + half * 8;
                size_t o = (size_t)r * Nn + c;
                float v0 = acc[mt][nt][half * 2 + 0] + b0;
                float v1 = acc[mt][nt][half * 2 + 1] + b1;
                if (RES) { v0 += res[o]; v1 += res[o + 1]; }
                if (RELU) { v0 = fmaxf(v0, 0.f); v1 = fmaxf(v1, 0.f); }
                if (RNDO) { v0 = tfround(v0); v1 = tfround(v1); }
                *(float2*)(C + o) = make_float2(v0, v1);
            }
        }
    }
}

// ---------------------------------------------------------------------------
// Tensor-core causal ReLU attention: y = (causal_relu(Q K^T / 8)) V
// Output rounded to tf32 (sole consumer is proj GEMM A).
// ---------------------------------------------------------------------------
__global__ void __launch_bounds__(128)
attn_tc_kernel(const float* __restrict__ qkv, float* __restrict__ y) {
    constexpr int QT = 64, KT = 32;
    __shared__ unsigned Qs[QT][68];
    __shared__ unsigned Ks[KT][68];
    __shared__ unsigned Vs[KT][72];
    __shared__ unsigned Ss[4][16][36];

    int q0 = blockIdx.x * QT;
    int h  = blockIdx.y;
    int b  = blockIdx.z;
    int tid = threadIdx.x, lane = tid & 31, w = tid >> 5;
    int g = lane >> 2, t4 = lane & 3;

    const size_t rs = 3 * D_;
    const float* base = qkv + (size_t)b * T_ * rs + h * HD_;

    // Load Q tile (64 x 64), convert to tf32
    {
        int c4 = (tid & 15) * 4, qr = tid >> 4;
#pragma unroll
        for (int p = 0; p < 8; p++) {
            int q = qr + p * 8;
            float4 v = *(const float4*)(base + (size_t)(q0 + q) * rs + c4);
            Qs[q][c4 + 0] = f2tf(v.x);
            Qs[q][c4 + 1] = f2tf(v.y);
            Qs[q][c4 + 2] = f2tf(v.z);
            Qs[q][c4 + 3] = f2tf(v.w);
        }
    }

    float oacc[8][4] = {};
    int qa = q0 + w * 16 + g;   // absolute q of c-rows 0/1 (row g)

    for (int kbase = 0; kbase < q0 + QT; kbase += KT) {
        __syncthreads();   // prior-iter PV done with Ks/Vs; Q ready on iter 0
        {
            int c4 = (tid & 15) * 4, kr = tid >> 4;
#pragma unroll
            for (int p = 0; p < 4; p++) {
                int k = kr + p * 8;
                const float* rp = base + (size_t)(kbase + k) * rs + c4;
                float4 kv = *(const float4*)(rp + D_);
                float4 vv = *(const float4*)(rp + 2 * D_);
                Ks[k][c4 + 0] = f2tf(kv.x);
                Ks[k][c4 + 1] = f2tf(kv.y);
                Ks[k][c4 + 2] = f2tf(kv.z);
                Ks[k][c4 + 3] = f2tf(kv.w);
                Vs[k][c4 + 0] = f2tf(vv.x);
                Vs[k][c4 + 1] = f2tf(vv.y);
                Vs[k][c4 + 2] = f2tf(vv.z);
                Vs[k][c4 + 3] = f2tf(vv.w);
            }
        }
        __syncthreads();

        // --- S = Q K^T (M=16, N=32, K=64) ---
        float sacc[4][4] = {};
#pragma unroll
        for (int ks = 0; ks < HD_; ks += 8) {
            unsigned a0 = Qs[w * 16 + g][ks + t4];
            unsigned a1 = Qs[w * 16 + g + 8][ks + t4];
            unsigned a2 = Qs[w * 16 + g][ks + t4 + 4];
            unsigned a3 = Qs[w * 16 + g + 8][ks + t4 + 4];
#pragma unroll
            for (int nt = 0; nt < 4; nt++) {
                unsigned b0 = Ks[nt * 8 + g][ks + t4];
                unsigned b1 = Ks[nt * 8 + g][ks + t4 + 4];
                asm volatile(
                    "mma.sync.aligned.m16n8k8.row.col.f32.tf32.tf32.f32 "
                    "{%0,%1,%2,%3}, {%4,%5,%6,%7}, {%8,%9}, {%0,%1,%2,%3};"
                    : "+f"(sacc[nt][0]), "+f"(sacc[nt][1]),
                      "+f"(sacc[nt][2]), "+f"(sacc[nt][3])
                    : "r"(a0), "r"(a1), "r"(a2), "r"(a3), "r"(b0), "r"(b1));
            }
        }

        // scale, causal mask, relu -> Ss (tf32)
#pragma unroll
        for (int nt = 0; nt < 4; nt++) {
            int ka = kbase + nt * 8 + 2 * t4;
            float s0 = (ka     <= qa)     ? fmaxf(sacc[nt][0] * 0.125f, 0.f) : 0.f;
            float s1 = (ka + 1 <= qa)     ? fmaxf(sacc[nt][1] * 0.125f, 0.f) : 0.f;
            float s2 = (ka     <= qa + 8) ? fmaxf(sacc[nt][2] * 0.125f, 0.f) : 0.f;
            float s3 = (ka + 1 <= qa + 8) ? fmaxf(sacc[nt][3] * 0.125f, 0.f) : 0.f;
            Ss[w][g][nt * 8 + 2 * t4]         = f2tf(s0);
            Ss[w][g][nt * 8 + 2 * t4 + 1]     = f2tf(s1);
            Ss[w][g + 8][nt * 8 + 2 * t4]     = f2tf(s2);
            Ss[w][g + 8][nt * 8 + 2 * t4 + 1] = f2tf(s3);
        }
        __syncwarp();

        // --- oacc += S @ V (M=16, N=64, K=32) ---
#pragma unroll
        for (int ks = 0; ks < KT; ks += 8) {
            unsigned a0 = Ss[w][g][ks + t4];
            unsigned a1 = Ss[w][g + 8][ks + t4];
            unsigned a2 = Ss[w][g][ks + t4 + 4];
            unsigned a3 = Ss[w][g + 8][ks + t4 + 4];
#pragma unroll
            for (int nt = 0; nt < 8; nt++) {
                unsigned b0 = Vs[ks + t4][nt * 8 + g];
                unsigned b1 = Vs[ks + t4 + 4][nt * 8 + g];
                asm volatile(
                    "mma.sync.aligned.m16n8k8.row.col.f32.tf32.tf32.f32 "
                    "{%0,%1,%2,%3}, {%4,%5,%6,%7}, {%8,%9}, {%0,%1,%2,%3};"
                    : "+f"(oacc[nt][0]), "+f"(oacc[nt][1]),
                      "+f"(oacc[nt][2]), "+f"(oacc[nt][3])
                    : "r"(a0), "r"(a1), "r"(a2), "r"(a3), "r"(b0), "r"(b1));
            }
        }
    }

    // epilogue: warp owns rows [w*16, w*16+16), cols [0, 64); round to tf32
    float* yb = y + ((size_t)(b * T_ + q0 + w * 16) * D_) + h * HD_;
#pragma unroll
    for (int nt = 0; nt < 8; nt++) {
        int c = nt * 8 + 2 * t4;
        *(float2*)(yb + (size_t)g * D_ + c) =
            make_float2(tfround(oacc[nt][0]), tfround(oacc[nt][1]));
        *(float2*)(yb + (size_t)(g + 8) * D_ + c) =
            make_float2(tfround(oacc[nt][2]), tfround(oacc[nt][3]));
    }
}

// ---------------------------------------------------------------------------
// emb[b,d] = mean_t ln[b,t,d]
// ---------------------------------------------------------------------------
__global__ void mean_kernel(const float* __restrict__ ln,
                            float* __restrict__ embp) {
    int i = blockIdx.x * blockDim.x + threadIdx.x;
    if (i >= B_ * D_) return;
    int b = i >> 10, d = i & 1023;
    const float* p = ln + (size_t)b * T_ * D_ + d;
    float s = 0.f;
    for (int t = 0; t < T_; t++) s += p[(size_t)t * D_];
    embp[i] = s * (1.f / T_);
}

// ---------------------------------------------------------------------------
// logits = relu(emb @ head_w + head_b); store (logits - Y)^2
// ---------------------------------------------------------------------------
__global__ void head_kernel(const float* __restrict__ embp,
                            const float* __restrict__ hw,
                            const float* __restrict__ hb,
                            const float* __restrict__ Y) {
    int i = blockIdx.x * blockDim.x + threadIdx.x;
    if (i >= B_ * M_) return;
    int b = i / M_, m = i % M_;
    const float* e = embp + b * D_;
    float s = hb[m];
    for (int k = 0; k < D_; k++) s += e[k] * hw[k * M_ + m];
    s = fmaxf(s, 0.f);
    float df = s - Y[i];
    g_sq[i] = df * df;
}

// ---------------------------------------------------------------------------
// loss = 50 * sqrt(mean(sq))
// ---------------------------------------------------------------------------
__global__ void loss_kernel(float* __restrict__ outp) {
    __shared__ float sm[256];
    int tid = threadIdx.x;
    float s = 0.f;
    for (int i = tid; i < B_ * M_; i += 256) s += g_sq[i];
    sm[tid] = s;
    __syncthreads();
    for (int o = 128; o; o >>= 1) {
        if (tid < o) sm[tid] += sm[tid + o];
        __syncthreads();
    }
    if (tid == 0) outp[0] = 50.f * sqrtf(sm[0] / (float)(B_ * M_));
}

// ---------------------------------------------------------------------------
// Host driver (graph-capturable: kernel launches only)
// ---------------------------------------------------------------------------
extern "C" void kernel_launch(void* const* d_in, const int* in_sizes, int n_in,
                              void* d_out, int out_size) {
    const float* X      = (const float*)d_in[0];
    const float* Y      = (const float*)d_in[1];
    const float* wpe    = (const float*)d_in[2];
    const float* ln1_w  = (const float*)d_in[3];
    const float* ln1_b  = (const float*)d_in[4];
    const float* attn_w = (const float*)d_in[5];
    const float* attn_b = (const float*)d_in[6];
    const float* proj_w = (const float*)d_in[7];
    const float* proj_b = (const float*)d_in[8];
    const float* ln2_w  = (const float*)d_in[9];
    const float* ln2_b  = (const float*)d_in[10];
    const float* fc_w   = (const float*)d_in[11];
    const float* fc_b   = (const float*)d_in[12];
    const float* fcp_w  = (const float*)d_in[13];
    const float* fcp_b  = (const float*)d_in[14];
    const float* lnf_w  = (const float*)d_in[15];
    const float* lnf_b  = (const float*)d_in[16];
    const float* head_w = (const float*)d_in[17];
    const float* head_b = (const float*)d_in[18];
    float* out = (float*)d_out;

    float *x, *ln, *qkv, *attn, *ff, *emb;
    float *wqkv, *wprj, *wfc, *wfcp;
    cudaGetSymbolAddress((void**)&x,    g_x);
    cudaGetSymbolAddress((void**)&ln,   g_ln);
    cudaGetSymbolAddress((void**)&qkv,  g_qkv);
    cudaGetSymbolAddress((void**)&attn, g_attn);
    cudaGetSymbolAddress((void**)&ff,   g_ff);
    cudaGetSymbolAddress((void**)&emb,  g_emb);
    cudaGetSymbolAddress((void**)&wqkv, g_wqkv);
    cudaGetSymbolAddress((void**)&wprj, g_wprj);
    cudaGetSymbolAddress((void**)&wfc,  g_wfc);
    cudaGetSymbolAddress((void**)&wfcp, g_wfcp);

    cudaFuncSetAttribute(gemm_tf32_kernel<true, false, false>,
                         cudaFuncAttributeMaxDynamicSharedMemorySize, GEMM_SMEM);
    cudaFuncSetAttribute(gemm_tf32_kernel<true, false, true>,
                         cudaFuncAttributeMaxDynamicSharedMemorySize, GEMM_SMEM);
    cudaFuncSetAttribute(gemm_tf32_kernel<false, true, false>,
                         cudaFuncAttributeMaxDynamicSharedMemorySize, GEMM_SMEM);

    // one-time (per launch) weight rounding to tf32
    {
        int n;
        n = L_ * D_ * 3 * D_ / 4;
        round_kernel<<<(n + 255) / 256, 256>>>(attn_w, wqkv, n);
        n = L_ * D_ * D_ / 4;
        round_kernel<<<(n + 255) / 256, 256>>>(proj_w, wprj, n);
        n = L_ * D_ * 2 * D_ / 4;
        round_kernel<<<(n + 255) / 256, 256>>>(fc_w, wfc, n);
        n = L_ * 2 * D_ * D_ / 4;
        round_kernel<<<(n + 255) / 256, 256>>>(fcp_w, wfcp, n);
    }

    posadd_kernel<<<B_ * T_ * D_ / 256, 256>>>(X, wpe);

    dim3 gQKV(3 * D_ / 128, ROWS_ / 128);
    dim3 gD  (D_     / 128, ROWS_ / 128);
    dim3 gFF (2 * D_ / 128, ROWS_ / 128);
    dim3 gAtt(T_ / 64, H_, B_);

    for (int i = 0; i < L_; i++) {
        // x = relu(x); ln = tf32(LN(x))
        ln_kernel<true, true, false, true><<<ROWS_, 256>>>(
            x, x, ln1_w + i * D_, ln1_b + i * D_, ln);
        // qkv = relu(ln @ Wqkv + b)   (attn rounds q/k/v internally)
        gemm_tf32_kernel<true, false, false><<<gQKV, 256, GEMM_SMEM>>>(
            3 * D_, D_, ln,
            wqkv + (size_t)i * D_ * 3 * D_, attn_b + i * 3 * D_, nullptr, qkv);
        // y = tf32(causal-relu attention)
        attn_tc_kernel<<<gAtt, 128>>>(qkv, attn);
        // x = x + y @ Wproj + b   (residual: full fp32)
        gemm_tf32_kernel<false, true, false><<<gD, 256, GEMM_SMEM>>>(
            D_, D_, attn,
            wprj + (size_t)i * D_ * D_, proj_b + i * D_, x, x);
        // h = tf32(LN2(x))
        ln_kernel<false, false, false, true><<<ROWS_, 256>>>(
            x, nullptr, ln2_w + i * D_, ln2_b + i * D_, ln);
        // ff = tf32(relu(h @ Wfc + b))
        gemm_tf32_kernel<true, false, true><<<gFF, 256, GEMM_SMEM>>>(
            2 * D_, D_, ln,
            wfc + (size_t)i * D_ * 2 * D_, fc_b + i * 2 * D_, nullptr, ff);
        // x = x + ff @ Wfcp + b
        gemm_tf32_kernel<false, true, false><<<gD, 256, GEMM_SMEM>>>(
            D_, 2 * D_, ff,
            wfcp + (size_t)i * 2 * D_ * D_, fcp_b + i * D_, x, x);
    }

    // x = relu(x); ln = relu(LN_f(x))  -- NOT rounded (feeds emb output)
    ln_kernel<true, false, true, false><<<ROWS_, 256>>>(x, nullptr, lnf_w, lnf_b, ln);

    float* embp = (out_size >= B_ * D_) ? out : emb;
    mean_kernel<<<(B_ * D_ + 255) / 256, 256>>>(ln, embp);

    head_kernel<<<(B_ * M_ + 255) / 256, 256>>>(embp, head_w, head_b, Y);

    if (out_size >= B_ * D_ + 1) {
        loss_kernel<<<1, 256>>>(out + B_ * D_);
    } else if (out_size < B_ * D_) {
        loss_kernel<<<1, 256>>>(out);   // loss-only output layout
    }
}